// round 1
// baseline (speedup 1.0000x reference)
#include <cuda_runtime.h>

#define TPB 256

__global__ __launch_bounds__(TPB, 2)
void hop_invariant_kernel(const float* __restrict__ tf,
                          const float* __restrict__ C2,
                          const float* __restrict__ C3,
                          float* __restrict__ out,
                          int N)
{
    __shared__ float sC2[45];    // C2[i][j][m] at (i*3+j)*5 + m
    __shared__ float sC3[189];   // C3[i][j][k][m] at (i*9+j*3+k)*7 + m
    __shared__ float sO[TPB * 13];

    const int tid = threadIdx.x;
    if (tid < 45)  sC2[tid] = C2[tid];
    if (tid < 189) sC3[tid] = C3[tid];
    __syncthreads();

    const int n = blockIdx.x * TPB + tid;

    if (n < N) {
        // ---- load 16 features as 4x float4 ----
        const float4* p = reinterpret_cast<const float4*>(tf + (size_t)n * 16);
        float4 r0 = p[0], r1 = p[1], r2 = p[2], r3 = p[3];
        const float s  = r0.x;
        const float v0 = r0.y, v1 = r0.z, v2 = r0.w;
        float q[5];
        q[0] = r1.x; q[1] = r1.y; q[2] = r1.z; q[3] = r1.w; q[4] = r2.x;
        float t[7];
        t[0] = r2.y; t[1] = r2.z; t[2] = r2.w;
        t[3] = r3.x; t[4] = r3.y; t[5] = r3.z; t[6] = r3.w;
        float v[3] = {v0, v1, v2};

        // ---- a_half: ah[i][j] = sum_m C2[i][j][m] * q[m] ----
        float ah[9];
        #pragma unroll
        for (int r = 0; r < 9; r++) {
            float acc = 0.f;
            #pragma unroll
            for (int m = 0; m < 5; m++)
                acc = fmaf(sC2[r * 5 + m], q[m], acc);
            ah[r] = acc;
        }

        // ---- b_half: bh[i][j][k] = sum_m C3[i][j][k][m] * t[m] ----
        float bh[27];
        #pragma unroll
        for (int r = 0; r < 27; r++) {
            float acc = 0.f;
            #pragma unroll
            for (int m = 0; m < 7; m++)
                acc = fmaf(sC3[r * 7 + m], t[m], acc);
            bh[r] = acc;
        }

        // ---- a[j][k] = sum_i ah[i][j] * ah[i][k] ----
        float a[9];
        #pragma unroll
        for (int j = 0; j < 3; j++)
            #pragma unroll
            for (int k = 0; k < 3; k++) {
                float acc = 0.f;
                #pragma unroll
                for (int i = 0; i < 3; i++)
                    acc = fmaf(ah[i * 3 + j], ah[i * 3 + k], acc);
                a[j * 3 + k] = acc;
            }

        // ---- b[k][l] = sum_{i,j} bh[i][j][k] * bh[i][j][l] ----
        float b[9];
        #pragma unroll
        for (int k = 0; k < 3; k++)
            #pragma unroll
            for (int l = 0; l < 3; l++) {
                float acc = 0.f;
                #pragma unroll
                for (int ij = 0; ij < 9; ij++)
                    acc = fmaf(bh[ij * 3 + k], bh[ij * 3 + l], acc);
                b[k * 3 + l] = acc;
            }

        // ---- invariants ----
        const float I0 = s;
        const float I1 = v0 * v0 + v1 * v1 + v2 * v2;
        const float I2 = a[0] + a[4] + a[8];
        const float I4 = b[0] + b[4] + b[8];

        // I3 = sum a[r]*ah[r]; I10 = sum b[r]*ah[r]; I11 = sum a[r]*b[r]; I5 = sum b[r]^2
        float I3 = 0.f, I10 = 0.f, I11 = 0.f, I5 = 0.f;
        #pragma unroll
        for (int r = 0; r < 9; r++) {
            I3  = fmaf(a[r], ah[r], I3);
            I10 = fmaf(b[r], ah[r], I10);
            I11 = fmaf(a[r], b[r], I11);
            I5  = fmaf(b[r], b[r], I5);
        }

        // cvec[j] = sum_i ah[i][j] * v[i]
        float cv[3];
        #pragma unroll
        for (int j = 0; j < 3; j++) {
            float acc = 0.f;
            #pragma unroll
            for (int i = 0; i < 3; i++)
                acc = fmaf(ah[i * 3 + j], v[i], acc);
            cv[j] = acc;
        }
        const float I6 = cv[0] * v0 + cv[1] * v1 + cv[2] * v2;
        const float I7 = cv[0] * cv[0] + cv[1] * cv[1] + cv[2] * cv[2];

        // d[i][j] = sum_k bh[i][j][k] * v[k];  I8 = v^T d v;  I9 = v^T b v
        float I8 = 0.f, I9 = 0.f;
        #pragma unroll
        for (int i = 0; i < 3; i++)
            #pragma unroll
            for (int j = 0; j < 3; j++) {
                float dij = 0.f;
                #pragma unroll
                for (int k = 0; k < 3; k++)
                    dij = fmaf(bh[i * 9 + j * 3 + k], v[k], dij);
                I8 = fmaf(v[i] * v[j], dij, I8);
                I9 = fmaf(v[i] * v[j], b[i * 3 + j], I9);
            }

        // e[k] = sum_{ij} bh[i][j][k] * ah[i][j];  I12 = e.e
        float I12 = 0.f;
        #pragma unroll
        for (int k = 0; k < 3; k++) {
            float ek = 0.f;
            #pragma unroll
            for (int ij = 0; ij < 9; ij++)
                ek = fmaf(bh[ij * 3 + k], ah[ij], ek);
            I12 = fmaf(ek, ek, I12);
        }

        // stage into shared (stride 13: gcd(13,32)=1 -> conflict-free)
        float* so = &sO[tid * 13];
        so[0]  = I0;  so[1]  = I1;  so[2]  = I2;  so[3]  = I3;
        so[4]  = I4;  so[5]  = I5;  so[6]  = I6;  so[7]  = I7;
        so[8]  = I8;  so[9]  = I9;  so[10] = I10; so[11] = I11;
        so[12] = I12;
    }
    __syncthreads();

    // coalesced writeback of this block's contiguous output slab
    const int blk_start = blockIdx.x * TPB;
    int valid = N - blk_start;
    if (valid > TPB) valid = TPB;
    const int cnt = valid * 13;
    float* obase = out + (size_t)blk_start * 13;
    for (int i = tid; i < cnt; i += TPB)
        obase[i] = sO[i];
}

extern "C" void kernel_launch(void* const* d_in, const int* in_sizes, int n_in,
                              void* d_out, int out_size)
{
    const float* tf = (const float*)d_in[0];
    const float* C2 = (const float*)d_in[1];
    const float* C3 = (const float*)d_in[2];
    float* out = (float*)d_out;

    const int N = in_sizes[0] / 16;
    const int blocks = (N + TPB - 1) / TPB;
    hop_invariant_kernel<<<blocks, TPB>>>(tf, C2, C3, out, N);
}

// round 2
// speedup vs baseline: 1.0872x; 1.0872x over previous
#include <cuda_runtime.h>

#define TPB 256

__global__ __launch_bounds__(TPB, 3)
void hop_invariant_kernel(const float* __restrict__ tf,
                          const float* __restrict__ C2,
                          const float* __restrict__ C3,
                          float* __restrict__ out,
                          int N)
{
    __shared__ float sC2[45];    // C2[i][j][m] at (i*3+j)*5 + m
    __shared__ float sC3[189];   // C3[i][j][k][m] at (i*9+j*3+k)*7 + m
    __shared__ float sO[TPB * 13];

    const int tid = threadIdx.x;
    if (tid < 45)  sC2[tid] = C2[tid];
    if (tid < 189) sC3[tid] = C3[tid];
    __syncthreads();

    const int n = blockIdx.x * TPB + tid;

    if (n < N) {
        // ---- load 16 features as 4x float4 (MLP=4 up front) ----
        const float4* p = reinterpret_cast<const float4*>(tf + (size_t)n * 16);
        float4 r0 = p[0], r1 = p[1], r2 = p[2], r3 = p[3];
        const float s  = r0.x;
        float v[3] = {r0.y, r0.z, r0.w};
        float q[5] = {r1.x, r1.y, r1.z, r1.w, r2.x};
        float t[7] = {r2.y, r2.z, r2.w, r3.x, r3.y, r3.z, r3.w};

        // ---- ah[i][j] = sum_m C2[i][j][m] * q[m]  (q dies after this) ----
        float ah[9];
        #pragma unroll
        for (int r = 0; r < 9; r++) {
            float acc = 0.f;
            #pragma unroll
            for (int m = 0; m < 5; m++)
                acc = fmaf(sC2[r * 5 + m], q[m], acc);
            ah[r] = acc;
        }

        // ---- stream bh over outer index i; accumulate b (sym), e, I8 ----
        // b[k][l] = sum_{i,j} bh[i][j][k] * bh[i][j][l]   (symmetric: 6 accums)
        // e[k]    = sum_{i,j} bh[i][j][k] * ah[i][j]
        // I8      = sum_{i,j,k} bh[i][j][k] * v[i] v[j] v[k]
        float b00 = 0.f, b01 = 0.f, b02 = 0.f, b11 = 0.f, b12 = 0.f, b22 = 0.f;
        float e0 = 0.f, e1 = 0.f, e2 = 0.f;
        float I8 = 0.f;

        #pragma unroll
        for (int i = 0; i < 3; i++) {
            float bh[9];   // bh[i][j][k] for this i, at j*3+k
            #pragma unroll
            for (int r = 0; r < 9; r++) {
                float acc = 0.f;
                #pragma unroll
                for (int m = 0; m < 7; m++)
                    acc = fmaf(sC3[(i * 9 + r) * 7 + m], t[m], acc);
                bh[r] = acc;
            }

            float i8i = 0.f;
            #pragma unroll
            for (int j = 0; j < 3; j++) {
                const float* bj = &bh[j * 3];
                // symmetric Gram accumulation
                b00 = fmaf(bj[0], bj[0], b00);
                b01 = fmaf(bj[0], bj[1], b01);
                b02 = fmaf(bj[0], bj[2], b02);
                b11 = fmaf(bj[1], bj[1], b11);
                b12 = fmaf(bj[1], bj[2], b12);
                b22 = fmaf(bj[2], bj[2], b22);
                // e[k] += bh[i][j][k] * ah[i][j]
                const float ahij = ah[i * 3 + j];
                e0 = fmaf(bj[0], ahij, e0);
                e1 = fmaf(bj[1], ahij, e1);
                e2 = fmaf(bj[2], ahij, e2);
                // I8 partial
                float dj = bj[0] * v[0];
                dj = fmaf(bj[1], v[1], dj);
                dj = fmaf(bj[2], v[2], dj);
                i8i = fmaf(v[j], dj, i8i);
            }
            I8 = fmaf(v[i], i8i, I8);
        }
        // t is dead now.

        // ---- a[j][k] = sum_i ah[i][j] ah[i][k]  (symmetric: 6 scalars) ----
        float a00 = 0.f, a01 = 0.f, a02 = 0.f, a11 = 0.f, a12 = 0.f, a22 = 0.f;
        #pragma unroll
        for (int i = 0; i < 3; i++) {
            const float x = ah[i * 3 + 0], y = ah[i * 3 + 1], z = ah[i * 3 + 2];
            a00 = fmaf(x, x, a00); a01 = fmaf(x, y, a01); a02 = fmaf(x, z, a02);
            a11 = fmaf(y, y, a11); a12 = fmaf(y, z, a12); a22 = fmaf(z, z, a22);
        }

        // ---- scalar invariants ----
        const float I0 = s;
        const float I1 = v[0]*v[0] + v[1]*v[1] + v[2]*v[2];
        const float I2 = a00 + a11 + a22;
        const float I4 = b00 + b11 + b22;

        // I3 = sum_{jk} a[jk] ah[jk]  (a symmetric, ah not)
        const float I3 = a00*ah[0] + a11*ah[4] + a22*ah[8]
                       + a01*(ah[1] + ah[3]) + a02*(ah[2] + ah[6]) + a12*(ah[5] + ah[7]);
        // I10 = sum_{kl} b[kl] ah[kl]
        const float I10 = b00*ah[0] + b11*ah[4] + b22*ah[8]
                        + b01*(ah[1] + ah[3]) + b02*(ah[2] + ah[6]) + b12*(ah[5] + ah[7]);
        // I11 = sum a.b (both symmetric)
        const float I11 = a00*b00 + a11*b11 + a22*b22
                        + 2.f*(a01*b01 + a02*b02 + a12*b12);
        // I5 = sum b^2
        const float I5 = b00*b00 + b11*b11 + b22*b22
                       + 2.f*(b01*b01 + b02*b02 + b12*b12);
        // I9 = v^T b v
        const float I9 = v[0]*v[0]*b00 + v[1]*v[1]*b11 + v[2]*v[2]*b22
                       + 2.f*(v[0]*v[1]*b01 + v[0]*v[2]*b02 + v[1]*v[2]*b12);

        // cv[j] = sum_i ah[i][j] v[i]
        float cv0 = ah[0]*v[0], cv1 = ah[1]*v[0], cv2 = ah[2]*v[0];
        cv0 = fmaf(ah[3], v[1], cv0); cv1 = fmaf(ah[4], v[1], cv1); cv2 = fmaf(ah[5], v[1], cv2);
        cv0 = fmaf(ah[6], v[2], cv0); cv1 = fmaf(ah[7], v[2], cv1); cv2 = fmaf(ah[8], v[2], cv2);
        const float I6 = cv0*v[0] + cv1*v[1] + cv2*v[2];
        const float I7 = cv0*cv0 + cv1*cv1 + cv2*cv2;

        const float I12 = e0*e0 + e1*e1 + e2*e2;

        // stage into shared (stride 13: gcd(13,32)=1 -> conflict-free)
        float* so = &sO[tid * 13];
        so[0]  = I0;  so[1]  = I1;  so[2]  = I2;  so[3]  = I3;
        so[4]  = I4;  so[5]  = I5;  so[6]  = I6;  so[7]  = I7;
        so[8]  = I8;  so[9]  = I9;  so[10] = I10; so[11] = I11;
        so[12] = I12;
    }
    __syncthreads();

    // coalesced writeback of this block's contiguous output slab
    const int blk_start = blockIdx.x * TPB;
    int valid = N - blk_start;
    if (valid > TPB) valid = TPB;
    const int cnt = valid * 13;
    float* obase = out + (size_t)blk_start * 13;
    for (int i = tid; i < cnt; i += TPB)
        obase[i] = sO[i];
}

extern "C" void kernel_launch(void* const* d_in, const int* in_sizes, int n_in,
                              void* d_out, int out_size)
{
    const float* tf = (const float*)d_in[0];
    const float* C2 = (const float*)d_in[1];
    const float* C3 = (const float*)d_in[2];
    float* out = (float*)d_out;

    const int N = in_sizes[0] / 16;
    const int blocks = (N + TPB - 1) / TPB;
    hop_invariant_kernel<<<blocks, TPB>>>(tf, C2, C3, out, N);
}

// round 3
// speedup vs baseline: 1.1611x; 1.0680x over previous
#include <cuda_runtime.h>

#define TPB 256

__global__ __launch_bounds__(TPB, 3)
void hop_invariant_kernel(const float* __restrict__ tf,
                          const float* __restrict__ C2,
                          const float* __restrict__ C3,
                          float* __restrict__ out,
                          int N)
{
    // padded, 16B-aligned constant tiles: row stride 8 floats
    __shared__ __align__(16) float sC2p[9 * 8];    // C2[r][m], m<5 valid
    __shared__ __align__(16) float sC3p[27 * 8];   // C3[r][m], m<7 valid
    __shared__ __align__(16) float sO[TPB * 13];

    const int tid = threadIdx.x;
    if (tid < 72) {
        int r = tid >> 3, m = tid & 7;
        sC2p[tid] = (m < 5) ? C2[r * 5 + m] : 0.f;
    }
    if (tid < 216) {
        int r = tid >> 3, m = tid & 7;
        sC3p[tid] = (m < 7) ? C3[r * 7 + m] : 0.f;
    }
    __syncthreads();

    const int n = blockIdx.x * TPB + tid;

    if (n < N) {
        // ---- load 16 features as 4x float4 ----
        const float4* p = reinterpret_cast<const float4*>(tf + (size_t)n * 16);
        float4 r0 = p[0], r1 = p[1], r2 = p[2], r3 = p[3];
        const float s  = r0.x;
        float v[3] = {r0.y, r0.z, r0.w};
        const float q0 = r1.x, q1 = r1.y, q2 = r1.z, q3 = r1.w, q4 = r2.x;
        const float t0 = r2.y, t1 = r2.z, t2 = r2.w,
                    t3 = r3.x, t4 = r3.y, t5 = r3.z, t6 = r3.w;

        // ---- ah[r] = sum_m C2[r][m] * q[m]  (vector const loads) ----
        float ah[9];
        #pragma unroll
        for (int r = 0; r < 9; r++) {
            const float4 cA = *reinterpret_cast<const float4*>(&sC2p[r * 8]);
            const float  c4 = sC2p[r * 8 + 4];
            float acc = cA.x * q0;
            acc = fmaf(cA.y, q1, acc);
            acc = fmaf(cA.z, q2, acc);
            acc = fmaf(cA.w, q3, acc);
            acc = fmaf(c4,   q4, acc);
            ah[r] = acc;
        }

        // ---- stream bh over outer index i; accumulate b (sym), e, I8 ----
        float b00 = 0.f, b01 = 0.f, b02 = 0.f, b11 = 0.f, b12 = 0.f, b22 = 0.f;
        float e0 = 0.f, e1 = 0.f, e2 = 0.f;
        float I8 = 0.f;

        #pragma unroll
        for (int i = 0; i < 3; i++) {
            float bh[9];   // bh[i][j][k] at j*3+k for this i
            #pragma unroll
            for (int r = 0; r < 9; r++) {
                const int base = (i * 9 + r) * 8;
                const float4 cA = *reinterpret_cast<const float4*>(&sC3p[base]);
                const float4 cB = *reinterpret_cast<const float4*>(&sC3p[base + 4]);
                float acc = cA.x * t0;
                acc = fmaf(cA.y, t1, acc);
                acc = fmaf(cA.z, t2, acc);
                acc = fmaf(cA.w, t3, acc);
                acc = fmaf(cB.x, t4, acc);
                acc = fmaf(cB.y, t5, acc);
                acc = fmaf(cB.z, t6, acc);
                bh[r] = acc;
            }

            float i8i = 0.f;
            #pragma unroll
            for (int j = 0; j < 3; j++) {
                const float bj0 = bh[j * 3 + 0], bj1 = bh[j * 3 + 1], bj2 = bh[j * 3 + 2];
                b00 = fmaf(bj0, bj0, b00);
                b01 = fmaf(bj0, bj1, b01);
                b02 = fmaf(bj0, bj2, b02);
                b11 = fmaf(bj1, bj1, b11);
                b12 = fmaf(bj1, bj2, b12);
                b22 = fmaf(bj2, bj2, b22);
                const float ahij = ah[i * 3 + j];
                e0 = fmaf(bj0, ahij, e0);
                e1 = fmaf(bj1, ahij, e1);
                e2 = fmaf(bj2, ahij, e2);
                float dj = bj0 * v[0];
                dj = fmaf(bj1, v[1], dj);
                dj = fmaf(bj2, v[2], dj);
                i8i = fmaf(v[j], dj, i8i);
            }
            I8 = fmaf(v[i], i8i, I8);
        }

        // ---- a[j][k] = sum_i ah[i][j] ah[i][k]  (symmetric) ----
        float a00 = 0.f, a01 = 0.f, a02 = 0.f, a11 = 0.f, a12 = 0.f, a22 = 0.f;
        #pragma unroll
        for (int i = 0; i < 3; i++) {
            const float x = ah[i * 3 + 0], y = ah[i * 3 + 1], z = ah[i * 3 + 2];
            a00 = fmaf(x, x, a00); a01 = fmaf(x, y, a01); a02 = fmaf(x, z, a02);
            a11 = fmaf(y, y, a11); a12 = fmaf(y, z, a12); a22 = fmaf(z, z, a22);
        }

        // ---- invariants ----
        const float I0 = s;
        const float I1 = v[0]*v[0] + v[1]*v[1] + v[2]*v[2];
        const float I2 = a00 + a11 + a22;
        const float I4 = b00 + b11 + b22;

        const float I3 = a00*ah[0] + a11*ah[4] + a22*ah[8]
                       + a01*(ah[1] + ah[3]) + a02*(ah[2] + ah[6]) + a12*(ah[5] + ah[7]);
        const float I10 = b00*ah[0] + b11*ah[4] + b22*ah[8]
                        + b01*(ah[1] + ah[3]) + b02*(ah[2] + ah[6]) + b12*(ah[5] + ah[7]);
        const float I11 = a00*b00 + a11*b11 + a22*b22
                        + 2.f*(a01*b01 + a02*b02 + a12*b12);
        const float I5 = b00*b00 + b11*b11 + b22*b22
                       + 2.f*(b01*b01 + b02*b02 + b12*b12);
        const float I9 = v[0]*v[0]*b00 + v[1]*v[1]*b11 + v[2]*v[2]*b22
                       + 2.f*(v[0]*v[1]*b01 + v[0]*v[2]*b02 + v[1]*v[2]*b12);

        float cv0 = ah[0]*v[0], cv1 = ah[1]*v[0], cv2 = ah[2]*v[0];
        cv0 = fmaf(ah[3], v[1], cv0); cv1 = fmaf(ah[4], v[1], cv1); cv2 = fmaf(ah[5], v[1], cv2);
        cv0 = fmaf(ah[6], v[2], cv0); cv1 = fmaf(ah[7], v[2], cv1); cv2 = fmaf(ah[8], v[2], cv2);
        const float I6 = cv0*v[0] + cv1*v[1] + cv2*v[2];
        const float I7 = cv0*cv0 + cv1*cv1 + cv2*cv2;

        const float I12 = e0*e0 + e1*e1 + e2*e2;

        float* so = &sO[tid * 13];
        so[0]  = I0;  so[1]  = I1;  so[2]  = I2;  so[3]  = I3;
        so[4]  = I4;  so[5]  = I5;  so[6]  = I6;  so[7]  = I7;
        so[8]  = I8;  so[9]  = I9;  so[10] = I10; so[11] = I11;
        so[12] = I12;
    }
    __syncthreads();

    // coalesced writeback: full blocks go vectorized (float4), tail scalar
    const int blk_start = blockIdx.x * TPB;
    const int valid = min(N - blk_start, TPB);
    float* obase = out + (size_t)blk_start * 13;

    if (valid == TPB) {
        // TPB*13 floats = TPB*13/4 float4 (256*13 = 3328 = 832*4), base 16B-aligned
        const float4* src = reinterpret_cast<const float4*>(sO);
        float4* dst = reinterpret_cast<float4*>(obase);
        #pragma unroll
        for (int i = tid; i < (TPB * 13) / 4; i += TPB)
            dst[i] = src[i];
    } else {
        const int cnt = valid * 13;
        for (int i = tid; i < cnt; i += TPB)
            obase[i] = sO[i];
    }
}

extern "C" void kernel_launch(void* const* d_in, const int* in_sizes, int n_in,
                              void* d_out, int out_size)
{
    const float* tf = (const float*)d_in[0];
    const float* C2 = (const float*)d_in[1];
    const float* C3 = (const float*)d_in[2];
    float* out = (float*)d_out;

    const int N = in_sizes[0] / 16;
    const int blocks = (N + TPB - 1) / TPB;
    hop_invariant_kernel<<<blocks, TPB>>>(tf, C2, C3, out, N);
}

// round 4
// speedup vs baseline: 1.3597x; 1.1710x over previous
#include <cuda_runtime.h>

#define TPB 256

__constant__ float cC2[45];    // C2[i][j][m] at (i*3+j)*5 + m
__constant__ float cC3[189];   // C3[i][j][k][m] at (i*9+j*3+k)*7 + m

__global__ __launch_bounds__(TPB, 3)
void hop_invariant_kernel(const float* __restrict__ tf,
                          float* __restrict__ out,
                          int N)
{
    __shared__ __align__(16) float sO[TPB * 13];

    const int tid = threadIdx.x;
    const int n = blockIdx.x * TPB + tid;

    if (n < N) {
        // ---- load 16 features as 4x float4 ----
        const float4* p = reinterpret_cast<const float4*>(tf + (size_t)n * 16);
        float4 r0 = p[0], r1 = p[1], r2 = p[2], r3 = p[3];
        const float s  = r0.x;
        float v[3] = {r0.y, r0.z, r0.w};
        const float q0 = r1.x, q1 = r1.y, q2 = r1.z, q3 = r1.w, q4 = r2.x;
        float t[7] = {r2.y, r2.z, r2.w, r3.x, r3.y, r3.z, r3.w};

        // ---- ah[r] = sum_m C2[r][m] * q[m]  (constants via const bank) ----
        float ah[9];
        #pragma unroll
        for (int r = 0; r < 9; r++) {
            float acc =      cC2[r * 5 + 0] * q0;
            acc = fmaf(cC2[r * 5 + 1], q1, acc);
            acc = fmaf(cC2[r * 5 + 2], q2, acc);
            acc = fmaf(cC2[r * 5 + 3], q3, acc);
            acc = fmaf(cC2[r * 5 + 4], q4, acc);
            ah[r] = acc;
        }

        // ---- stream bh over outer index i; accumulate b (sym), e, I8 ----
        float b00 = 0.f, b01 = 0.f, b02 = 0.f, b11 = 0.f, b12 = 0.f, b22 = 0.f;
        float e0 = 0.f, e1 = 0.f, e2 = 0.f;
        float I8 = 0.f;

        #pragma unroll
        for (int i = 0; i < 3; i++) {
            float bh[9];   // bh[i][j][k] at j*3+k for this i
            #pragma unroll
            for (int r = 0; r < 9; r++) {
                const int base = (i * 9 + r) * 7;
                float acc = cC3[base + 0] * t[0];
                #pragma unroll
                for (int m = 1; m < 7; m++)
                    acc = fmaf(cC3[base + m], t[m], acc);
                bh[r] = acc;
            }

            float i8i = 0.f;
            #pragma unroll
            for (int j = 0; j < 3; j++) {
                const float bj0 = bh[j * 3 + 0], bj1 = bh[j * 3 + 1], bj2 = bh[j * 3 + 2];
                b00 = fmaf(bj0, bj0, b00);
                b01 = fmaf(bj0, bj1, b01);
                b02 = fmaf(bj0, bj2, b02);
                b11 = fmaf(bj1, bj1, b11);
                b12 = fmaf(bj1, bj2, b12);
                b22 = fmaf(bj2, bj2, b22);
                const float ahij = ah[i * 3 + j];
                e0 = fmaf(bj0, ahij, e0);
                e1 = fmaf(bj1, ahij, e1);
                e2 = fmaf(bj2, ahij, e2);
                float dj = bj0 * v[0];
                dj = fmaf(bj1, v[1], dj);
                dj = fmaf(bj2, v[2], dj);
                i8i = fmaf(v[j], dj, i8i);
            }
            I8 = fmaf(v[i], i8i, I8);
        }

        // ---- a[j][k] = sum_i ah[i][j] ah[i][k]  (symmetric) ----
        float a00 = 0.f, a01 = 0.f, a02 = 0.f, a11 = 0.f, a12 = 0.f, a22 = 0.f;
        #pragma unroll
        for (int i = 0; i < 3; i++) {
            const float x = ah[i * 3 + 0], y = ah[i * 3 + 1], z = ah[i * 3 + 2];
            a00 = fmaf(x, x, a00); a01 = fmaf(x, y, a01); a02 = fmaf(x, z, a02);
            a11 = fmaf(y, y, a11); a12 = fmaf(y, z, a12); a22 = fmaf(z, z, a22);
        }

        // ---- invariants ----
        const float I0 = s;
        const float I1 = v[0]*v[0] + v[1]*v[1] + v[2]*v[2];
        const float I2 = a00 + a11 + a22;
        const float I4 = b00 + b11 + b22;

        const float I3 = a00*ah[0] + a11*ah[4] + a22*ah[8]
                       + a01*(ah[1] + ah[3]) + a02*(ah[2] + ah[6]) + a12*(ah[5] + ah[7]);
        const float I10 = b00*ah[0] + b11*ah[4] + b22*ah[8]
                        + b01*(ah[1] + ah[3]) + b02*(ah[2] + ah[6]) + b12*(ah[5] + ah[7]);
        const float I11 = a00*b00 + a11*b11 + a22*b22
                        + 2.f*(a01*b01 + a02*b02 + a12*b12);
        const float I5 = b00*b00 + b11*b11 + b22*b22
                       + 2.f*(b01*b01 + b02*b02 + b12*b12);
        const float I9 = v[0]*v[0]*b00 + v[1]*v[1]*b11 + v[2]*v[2]*b22
                       + 2.f*(v[0]*v[1]*b01 + v[0]*v[2]*b02 + v[1]*v[2]*b12);

        float cv0 = ah[0]*v[0], cv1 = ah[1]*v[0], cv2 = ah[2]*v[0];
        cv0 = fmaf(ah[3], v[1], cv0); cv1 = fmaf(ah[4], v[1], cv1); cv2 = fmaf(ah[5], v[1], cv2);
        cv0 = fmaf(ah[6], v[2], cv0); cv1 = fmaf(ah[7], v[2], cv1); cv2 = fmaf(ah[8], v[2], cv2);
        const float I6 = cv0*v[0] + cv1*v[1] + cv2*v[2];
        const float I7 = cv0*cv0 + cv1*cv1 + cv2*cv2;

        const float I12 = e0*e0 + e1*e1 + e2*e2;

        float* so = &sO[tid * 13];
        so[0]  = I0;  so[1]  = I1;  so[2]  = I2;  so[3]  = I3;
        so[4]  = I4;  so[5]  = I5;  so[6]  = I6;  so[7]  = I7;
        so[8]  = I8;  so[9]  = I9;  so[10] = I10; so[11] = I11;
        so[12] = I12;
    }
    __syncthreads();

    // coalesced writeback: full blocks vectorized (float4), tail scalar
    const int blk_start = blockIdx.x * TPB;
    const int valid = min(N - blk_start, TPB);
    float* obase = out + (size_t)blk_start * 13;

    if (valid == TPB) {
        const float4* src = reinterpret_cast<const float4*>(sO);
        float4* dst = reinterpret_cast<float4*>(obase);
        #pragma unroll
        for (int i = tid; i < (TPB * 13) / 4; i += TPB)
            dst[i] = src[i];
    } else {
        const int cnt = valid * 13;
        for (int i = tid; i < cnt; i += TPB)
            obase[i] = sO[i];
    }
}

extern "C" void kernel_launch(void* const* d_in, const int* in_sizes, int n_in,
                              void* d_out, int out_size)
{
    const float* tf = (const float*)d_in[0];
    const float* C2 = (const float*)d_in[1];
    const float* C3 = (const float*)d_in[2];
    float* out = (float*)d_out;

    // stage coupling constants into the constant bank (graph-capturable D2D memcpy nodes)
    cudaMemcpyToSymbolAsync(cC2, C2, 45 * sizeof(float), 0, cudaMemcpyDeviceToDevice);
    cudaMemcpyToSymbolAsync(cC3, C3, 189 * sizeof(float), 0, cudaMemcpyDeviceToDevice);

    const int N = in_sizes[0] / 16;
    const int blocks = (N + TPB - 1) / TPB;
    hop_invariant_kernel<<<blocks, TPB>>>(tf, out, N);
}

// round 5
// speedup vs baseline: 1.4521x; 1.0679x over previous
#include <cuda_runtime.h>

#define TPB 192
#define PTS_PER_BLK (2 * TPB)

// one packed (c,c) float2 per coupling constant: [0,45) = C2, [45,234) = C3
__constant__ float2 cPack[234];
__device__ float2 gPack[234];

// ---------- packed f32x2 helpers (SASS FFMA2 path) ----------
typedef unsigned long long pf;

__device__ __forceinline__ pf f2fma(pf a, pf b, pf c) {
    pf d; asm("fma.rn.f32x2 %0, %1, %2, %3;" : "=l"(d) : "l"(a), "l"(b), "l"(c)); return d;
}
__device__ __forceinline__ pf f2mul(pf a, pf b) {
    pf d; asm("mul.rn.f32x2 %0, %1, %2;" : "=l"(d) : "l"(a), "l"(b)); return d;
}
__device__ __forceinline__ pf f2add(pf a, pf b) {
    pf d; asm("add.rn.f32x2 %0, %1, %2;" : "=l"(d) : "l"(a), "l"(b)); return d;
}
__device__ __forceinline__ pf f2pack(float lo, float hi) {
    pf d; asm("mov.b64 %0, {%1, %2};" : "=l"(d) : "f"(lo), "f"(hi)); return d;
}
__device__ __forceinline__ void f2unpack(pf p, float& lo, float& hi) {
    asm("mov.b64 {%0, %1}, %2;" : "=f"(lo), "=f"(hi) : "l"(p));
}

__global__ void prep_kernel(const float* __restrict__ C2, const float* __restrict__ C3) {
    int i = threadIdx.x;
    if (i < 45)       { float c = C2[i];      gPack[i] = make_float2(c, c); }
    else if (i < 234) { float c = C3[i - 45]; gPack[i] = make_float2(c, c); }
}

__global__ __launch_bounds__(TPB, 3)
void hop_invariant_kernel(const float* __restrict__ tf,
                          float* __restrict__ out,
                          int N)
{
    __shared__ __align__(16) float sO[PTS_PER_BLK * 13];

    const unsigned long long* cp = reinterpret_cast<const unsigned long long*>(cPack);
#define C2P(i) cp[i]
#define C3P(i) cp[45 + (i)]

    const int tid = threadIdx.x;
    const int blk_start = blockIdx.x * PTS_PER_BLK;
    const int nA = blk_start + tid;
    const int nB = nA + TPB;

    if (nA < N) {
        // ---- load 16 features for both points (up to 8 LDG.128 in flight) ----
        float4 a0 = make_float4(0,0,0,0), a1 = a0, a2 = a0, a3 = a0;
        float4 b0 = a0, b1 = a0, b2 = a0, b3 = a0;
        {
            const float4* pA = reinterpret_cast<const float4*>(tf + (size_t)nA * 16);
            a0 = pA[0]; a1 = pA[1]; a2 = pA[2]; a3 = pA[3];
        }
        if (nB < N) {
            const float4* pB = reinterpret_cast<const float4*>(tf + (size_t)nB * 16);
            b0 = pB[0]; b1 = pB[1]; b2 = pB[2]; b3 = pB[3];
        }

        // ---- pack lanes: lo = point A, hi = point B ----
        const pf s  = f2pack(a0.x, b0.x);
        pf v[3] = { f2pack(a0.y, b0.y), f2pack(a0.z, b0.z), f2pack(a0.w, b0.w) };
        const pf q0 = f2pack(a1.x, b1.x), q1 = f2pack(a1.y, b1.y),
                 q2 = f2pack(a1.z, b1.z), q3 = f2pack(a1.w, b1.w),
                 q4 = f2pack(a2.x, b2.x);
        pf t[7] = { f2pack(a2.y, b2.y), f2pack(a2.z, b2.z), f2pack(a2.w, b2.w),
                    f2pack(a3.x, b3.x), f2pack(a3.y, b3.y), f2pack(a3.z, b3.z),
                    f2pack(a3.w, b3.w) };

        // ---- ah[r] = sum_m C2[r][m] * q[m] ----
        pf ah[9];
        #pragma unroll
        for (int r = 0; r < 9; r++) {
            pf acc = f2mul(C2P(r * 5 + 0), q0);
            acc = f2fma(C2P(r * 5 + 1), q1, acc);
            acc = f2fma(C2P(r * 5 + 2), q2, acc);
            acc = f2fma(C2P(r * 5 + 3), q3, acc);
            acc = f2fma(C2P(r * 5 + 4), q4, acc);
            ah[r] = acc;
        }

        // ---- stream bh over i; accumulate b (sym), e, I8 ----
        pf b00 = 0, b01 = 0, b02 = 0, b11 = 0, b12 = 0, b22 = 0;
        pf e0 = 0, e1 = 0, e2 = 0;
        pf I8 = 0;

        #pragma unroll
        for (int i = 0; i < 3; i++) {
            pf bh[9];
            #pragma unroll
            for (int r = 0; r < 9; r++) {
                const int base = (i * 9 + r) * 7;
                pf acc = f2mul(C3P(base + 0), t[0]);
                acc = f2fma(C3P(base + 1), t[1], acc);
                acc = f2fma(C3P(base + 2), t[2], acc);
                acc = f2fma(C3P(base + 3), t[3], acc);
                acc = f2fma(C3P(base + 4), t[4], acc);
                acc = f2fma(C3P(base + 5), t[5], acc);
                acc = f2fma(C3P(base + 6), t[6], acc);
                bh[r] = acc;
            }

            pf i8i = 0;
            #pragma unroll
            for (int j = 0; j < 3; j++) {
                const pf bj0 = bh[j * 3 + 0], bj1 = bh[j * 3 + 1], bj2 = bh[j * 3 + 2];
                b00 = f2fma(bj0, bj0, b00);
                b01 = f2fma(bj0, bj1, b01);
                b02 = f2fma(bj0, bj2, b02);
                b11 = f2fma(bj1, bj1, b11);
                b12 = f2fma(bj1, bj2, b12);
                b22 = f2fma(bj2, bj2, b22);
                const pf ahij = ah[i * 3 + j];
                e0 = f2fma(bj0, ahij, e0);
                e1 = f2fma(bj1, ahij, e1);
                e2 = f2fma(bj2, ahij, e2);
                pf dj = f2mul(bj0, v[0]);
                dj = f2fma(bj1, v[1], dj);
                dj = f2fma(bj2, v[2], dj);
                i8i = f2fma(v[j], dj, i8i);
            }
            I8 = f2fma(v[i], i8i, I8);
        }

        // ---- a = ah^T ah (symmetric) ----
        pf a00 = 0, a01 = 0, a02 = 0, a11 = 0, a12 = 0, a22 = 0;
        #pragma unroll
        for (int i = 0; i < 3; i++) {
            const pf x = ah[i * 3 + 0], y = ah[i * 3 + 1], z = ah[i * 3 + 2];
            a00 = f2fma(x, x, a00); a01 = f2fma(x, y, a01); a02 = f2fma(x, z, a02);
            a11 = f2fma(y, y, a11); a12 = f2fma(y, z, a12); a22 = f2fma(z, z, a22);
        }

        // ---- invariants (packed) ----
        pf I1 = f2mul(v[0], v[0]);
        I1 = f2fma(v[1], v[1], I1);
        I1 = f2fma(v[2], v[2], I1);
        const pf I2 = f2add(f2add(a00, a11), a22);
        const pf I4 = f2add(f2add(b00, b11), b22);

        const pf sum13 = f2add(ah[1], ah[3]);
        const pf sum26 = f2add(ah[2], ah[6]);
        const pf sum57 = f2add(ah[5], ah[7]);

        pf I3 = f2mul(a00, ah[0]);
        I3 = f2fma(a11, ah[4], I3);
        I3 = f2fma(a22, ah[8], I3);
        I3 = f2fma(a01, sum13, I3);
        I3 = f2fma(a02, sum26, I3);
        I3 = f2fma(a12, sum57, I3);

        pf I10 = f2mul(b00, ah[0]);
        I10 = f2fma(b11, ah[4], I10);
        I10 = f2fma(b22, ah[8], I10);
        I10 = f2fma(b01, sum13, I10);
        I10 = f2fma(b02, sum26, I10);
        I10 = f2fma(b12, sum57, I10);

        pf w = f2mul(a01, b01);
        w = f2fma(a02, b02, w);
        w = f2fma(a12, b12, w);
        pf I11 = f2mul(a00, b00);
        I11 = f2fma(a11, b11, I11);
        I11 = f2fma(a22, b22, I11);
        I11 = f2add(I11, f2add(w, w));

        pf w5 = f2mul(b01, b01);
        w5 = f2fma(b02, b02, w5);
        w5 = f2fma(b12, b12, w5);
        pf I5 = f2mul(b00, b00);
        I5 = f2fma(b11, b11, I5);
        I5 = f2fma(b22, b22, I5);
        I5 = f2add(I5, f2add(w5, w5));

        const pf v01 = f2mul(v[0], v[1]);
        const pf v02 = f2mul(v[0], v[2]);
        const pf v12 = f2mul(v[1], v[2]);
        pf w9 = f2mul(v01, b01);
        w9 = f2fma(v02, b02, w9);
        w9 = f2fma(v12, b12, w9);
        pf I9 = f2mul(f2mul(v[0], v[0]), b00);
        I9 = f2fma(f2mul(v[1], v[1]), b11, I9);
        I9 = f2fma(f2mul(v[2], v[2]), b22, I9);
        I9 = f2add(I9, f2add(w9, w9));

        pf cv0 = f2mul(ah[0], v[0]);
        pf cv1 = f2mul(ah[1], v[0]);
        pf cv2 = f2mul(ah[2], v[0]);
        cv0 = f2fma(ah[3], v[1], cv0); cv1 = f2fma(ah[4], v[1], cv1); cv2 = f2fma(ah[5], v[1], cv2);
        cv0 = f2fma(ah[6], v[2], cv0); cv1 = f2fma(ah[7], v[2], cv1); cv2 = f2fma(ah[8], v[2], cv2);
        pf I6 = f2mul(cv0, v[0]);
        I6 = f2fma(cv1, v[1], I6);
        I6 = f2fma(cv2, v[2], I6);
        pf I7 = f2mul(cv0, cv0);
        I7 = f2fma(cv1, cv1, I7);
        I7 = f2fma(cv2, cv2, I7);

        pf I12 = f2mul(e0, e0);
        I12 = f2fma(e1, e1, I12);
        I12 = f2fma(e2, e2, I12);

        // ---- unpack and stage both points into shared ----
        const pf invs[13] = { s, I1, I2, I3, I4, I5, I6, I7, I8, I9, I10, I11, I12 };
        float* soA = &sO[tid * 13];
        float* soB = &sO[(tid + TPB) * 13];
        #pragma unroll
        for (int k = 0; k < 13; k++) {
            float lo, hi;
            f2unpack(invs[k], lo, hi);
            soA[k] = lo;
            soB[k] = hi;
        }
    }
    __syncthreads();

    // ---- coalesced writeback ----
    const int valid = min(N - blk_start, PTS_PER_BLK);
    float* obase = out + (size_t)blk_start * 13;

    if (valid == PTS_PER_BLK) {
        const float4* src = reinterpret_cast<const float4*>(sO);
        float4* dst = reinterpret_cast<float4*>(obase);
        #pragma unroll 4
        for (int i = tid; i < (PTS_PER_BLK * 13) / 4; i += TPB)
            dst[i] = src[i];
    } else {
        const int cnt = valid * 13;
        for (int i = tid; i < cnt; i += TPB)
            obase[i] = sO[i];
    }
#undef C2P
#undef C3P
}

extern "C" void kernel_launch(void* const* d_in, const int* in_sizes, int n_in,
                              void* d_out, int out_size)
{
    const float* tf = (const float*)d_in[0];
    const float* C2 = (const float*)d_in[1];
    const float* C3 = (const float*)d_in[2];
    float* out = (float*)d_out;

    // pack constants (c,c) -> constant bank: kernel node + one D2D memcpy node
    prep_kernel<<<1, 256>>>(C2, C3);
    void* gp = nullptr;
    cudaGetSymbolAddress(&gp, gPack);
    cudaMemcpyToSymbolAsync(cPack, gp, 234 * sizeof(float2), 0, cudaMemcpyDeviceToDevice);

    const int N = in_sizes[0] / 16;
    const int blocks = (N + PTS_PER_BLK - 1) / PTS_PER_BLK;
    hop_invariant_kernel<<<blocks, TPB>>>(tf, out, N);
}